// round 7
// baseline (speedup 1.0000x reference)
#include <cuda_runtime.h>
#include <math.h>

#define BB   128
#define VV   128000
#define NV4  (VV/4)
#define TPB  1024
#define NB   256
#define CAND_MAX 5120

// monotonic float -> ordered uint32
__device__ __forceinline__ unsigned f2ord(float f) {
    unsigned u = __float_as_uint(f);
    return (u & 0x80000000u) ? ~u : (u | 0x80000000u);
}
// inverse (floor decode); NaN-zone keys handled so bisection self-corrects
__device__ __forceinline__ float ord2f_floor(unsigned o) {
    if (o <= 0x007FFFFFu) return -__int_as_float(0x7f800000); // -inf: take all
    return (o & 0x80000000u) ? __uint_as_float(o ^ 0x80000000u)
                             : __uint_as_float(~o);
}

__device__ float blk_excl_scan(float v, float* tmp) {
    __syncthreads();
    int lane = threadIdx.x & 31, w = threadIdx.x >> 5;
    float x = v;
    #pragma unroll
    for (int o = 1; o < 32; o <<= 1) {
        float y = __shfl_up_sync(0xffffffffu, x, o);
        if (lane >= o) x += y;
    }
    if (lane == 31) tmp[w] = x;
    __syncthreads();
    if (w == 0) {
        float s = tmp[lane];
        #pragma unroll
        for (int o = 1; o < 32; o <<= 1) {
            float y = __shfl_up_sync(0xffffffffu, s, o);
            if (lane >= o) s += y;
        }
        tmp[lane] = s;
    }
    __syncthreads();
    float pre = (w > 0) ? tmp[w - 1] : 0.0f;
    return pre + x - v;
}

__device__ float blk_reduce_sum(float v, float* tmp) {
    __syncthreads();
    int lane = threadIdx.x & 31, w = threadIdx.x >> 5;
    #pragma unroll
    for (int o = 16; o; o >>= 1) v += __shfl_xor_sync(0xffffffffu, v, o);
    if (lane == 0) tmp[w] = v;
    __syncthreads();
    if (w == 0) {
        float x = tmp[lane];
        #pragma unroll
        for (int o = 16; o; o >>= 1) x += __shfl_xor_sync(0xffffffffu, x, o);
        if (lane == 0) tmp[0] = x;
    }
    __syncthreads();
    return tmp[0];
}

__device__ float blk_reduce_max(float v, float* tmp) {
    __syncthreads();
    int lane = threadIdx.x & 31, w = threadIdx.x >> 5;
    #pragma unroll
    for (int o = 16; o; o >>= 1) v = fmaxf(v, __shfl_xor_sync(0xffffffffu, v, o));
    if (lane == 0) tmp[w] = v;
    __syncthreads();
    if (w == 0) {
        float x = tmp[lane];
        #pragma unroll
        for (int o = 16; o; o >>= 1) x = fmaxf(x, __shfl_xor_sync(0xffffffffu, x, o));
        if (lane == 0) tmp[0] = x;
    }
    __syncthreads();
    return tmp[0];
}

struct CrossRes { int bin; float above; bool found; };

// 256-bin descending crossing: find bin c with cumAbove < target <= cumAbove+w[c]
__device__ CrossRes find_crossing256(const float* wgt, float target, float* scanTmp,
                                     int* sh_r, int* sh_b, float* sh_c) {
    __syncthreads();
    int t = threadIdx.x;
    float s = (t < NB) ? wgt[NB - 1 - t] : 0.f;
    float P = blk_excl_scan(s, scanTmp);
    if (t == 0) *sh_r = 0x7fffffff;
    __syncthreads();
    if (t < NB) {
        if (P < target && P + s >= target) atomicMin(sh_r, t);
    }
    __syncthreads();
    int fr = *sh_r;
    if (fr != 0x7fffffff && t == fr) { *sh_b = NB - 1 - t; *sh_c = P; }
    __syncthreads();
    CrossRes res;
    res.found = (fr != 0x7fffffff);
    res.bin = res.found ? *sh_b : 0;
    res.above = res.found ? *sh_c : 0.f;
    return res;
}

__global__ void __launch_bounds__(TPB, 1)
topk_topp_sample_kernel(const float* __restrict__ logits,
                        const int*   __restrict__ karr,
                        const float* __restrict__ parr,
                        const float* __restrict__ qarr,
                        float* __restrict__ out_ids,
                        float* __restrict__ out_probs)
{
    __shared__ float cand[CAND_MAX];      // 20 KB
    __shared__ int   candIdx[CAND_MAX];   // 20 KB
    __shared__ float h8[NB];              // 1 KB
    __shared__ float scanTmp[32];
    __shared__ float redTmp[32];
    __shared__ int   shr; __shared__ int shb; __shared__ float shc;
    __shared__ int   shn;
    __shared__ float argV[32]; __shared__ int argI[32];

    const int row = blockIdx.x;
    const int t = threadIdx.x;
    const int lane = t & 31, warp = t >> 5;
    const float* lg = logits + (long long)row * VV;
    const float* qr = qarr   + (long long)row * VV;
    float* pro = out_probs + (long long)row * VV;
    const int   k = karr[row];
    const float p = parr[row];

    const float4* lg4 = reinterpret_cast<const float4*>(lg);

    // ---- Phase A: speculative-floor ballot compaction + key bisection ----
    // (32000 mod 1024 = 256 = 8 full warps -> partial iteration is warp-uniform,
    //  so ballot with full mask is safe.)
    unsigned loK = 0u, hiK = 0xFFFFFFFFu, fK = 0xC0000000u;  // f2ord(2.0f)
    int n = 0;
    for (int iter = 0; iter < 12; iter++) {
        if (t == 0) shn = 0;
        __syncthreads();
        const float ffloor = ord2f_floor(fK);
        for (int i = t; i < NV4; i += TPB) {
            float4 v = lg4[i];
            float xs[4] = {v.x, v.y, v.z, v.w};
            #pragma unroll
            for (int j = 0; j < 4; j++) {
                float x = xs[j];
                bool take = (x >= ffloor);
                unsigned m = __ballot_sync(0xffffffffu, take);
                if (m) {
                    int leader = __ffs(m) - 1;
                    int base = 0;
                    if (lane == leader) base = atomicAdd(&shn, __popc(m));
                    base = __shfl_sync(0xffffffffu, base, leader);
                    if (take) {
                        int off = base + __popc(m & ((1u << lane) - 1u));
                        if (off < CAND_MAX) { cand[off] = x; candIdx[off] = i * 4 + j; }
                    }
                }
            }
        }
        __syncthreads();
        n = shn;
        if (n >= k && n <= CAND_MAX) break;
        if (n > CAND_MAX) { loK = fK; fK = fK + ((hiK - fK) >> 1); }
        else              { hiK = fK; fK = loK + ((fK - loK) >> 1); }
        __syncthreads();
    }
    if (n > CAND_MAX) n = CAND_MAX;

    // ---- Row max from candidates (global max is in cand) ----
    float mx = -3.4e38f;
    for (int i = t; i < n; i += TPB) mx = fmaxf(mx, cand[i]);
    float M = blk_reduce_max(mx, redTmp);

    // ---- Exact top-k threshold: 4-level 8-bit count radix on candidates ----
    unsigned pfx = 0u;
    float target = (float)k;
    #pragma unroll
    for (int level = 0; level < 4; level++) {
        const int shift = 24 - 8 * level;
        __syncthreads();
        if (t < NB) h8[t] = 0.f;
        __syncthreads();
        for (int i = t; i < n; i += TPB) {
            unsigned ou = f2ord(cand[i]);
            if (level == 0 || (ou >> (shift + 8)) == pfx)
                atomicAdd(&h8[(ou >> shift) & 255u], 1.f);
        }
        CrossRes cr = find_crossing256(h8, target, scanTmp, &shr, &shb, &shc);
        target -= cr.above;
        pfx = (pfx << 8) | (unsigned)cr.bin;
    }
    const unsigned thr_ou = pfx;

    // ---- Z_k over top-k set ----
    float zs = 0.f;
    for (int i = t; i < n; i += TPB) {
        float x = cand[i];
        if (f2ord(x) >= thr_ou) zs += __expf(x - M);
    }
    float Zk = blk_reduce_sum(zs, redTmp);
    float T = p * Zk;

    // ---- Weighted 4-level 8-bit radix descent for top-p cutoff ----
    unsigned t_ou = thr_ou;
    {
        unsigned wp = 0u;
        float tgt = T;
        bool done = false;
        #pragma unroll
        for (int level = 0; level < 4; level++) {
            if (done) break;
            const int shift = 24 - 8 * level;
            __syncthreads();
            if (t < NB) h8[t] = 0.f;
            __syncthreads();
            for (int i = t; i < n; i += TPB) {
                float x = cand[i];
                unsigned ou = f2ord(x);
                if (ou >= thr_ou && (level == 0 || (ou >> (shift + 8)) == wp))
                    atomicAdd(&h8[(ou >> shift) & 255u], __expf(x - M));
            }
            CrossRes cr = find_crossing256(h8, tgt, scanTmp, &shr, &shb, &shc);
            if (!cr.found) {
                t_ou = (level == 0) ? thr_ou : (wp << (shift + 8));
                done = true;
            } else {
                tgt -= cr.above;
                wp = (wp << 8) | (unsigned)cr.bin;
                if (level == 3) t_ou = wp;
            }
        }
    }
    const unsigned f_ou = (t_ou > thr_ou) ? t_ou : thr_ou;
    const float ford = ord2f_floor(f_ou);

    // ---- Final normalizer ----
    float zf = 0.f;
    for (int i = t; i < n; i += TPB) {
        float x = cand[i];
        if (x >= ford) zf += __expf(x - M);
    }
    float Z = blk_reduce_sum(zf, redTmp);
    float invZ = 1.0f / Z;

    // ---- Phase E1: stream zeros into probs (write-only) ----
    float4* pr4 = reinterpret_cast<float4*>(pro);
    const float4 z4 = make_float4(0.f, 0.f, 0.f, 0.f);
    for (int i = t; i < NV4; i += TPB) pr4[i] = z4;
    __syncthreads();

    // ---- Phase E2: sparse scatter of kept probs + Gumbel-max argmax ----
    float bv = -1.f; int bi = 0x7fffffff;
    for (int i = t; i < n; i += TPB) {
        float x = cand[i];
        if (x >= ford) {
            int idx = candIdx[i];
            float prob = __expf(x - M) * invZ;
            pro[idx] = prob;
            float ratio = prob / (-__logf(qr[idx]));
            if (ratio > bv || (ratio == bv && idx < bi)) { bv = ratio; bi = idx; }
        }
    }
    #pragma unroll
    for (int o = 16; o; o >>= 1) {
        float ov = __shfl_down_sync(0xffffffffu, bv, o);
        int   oi = __shfl_down_sync(0xffffffffu, bi, o);
        if (ov > bv || (ov == bv && oi < bi)) { bv = ov; bi = oi; }
    }
    if (lane == 0) { argV[warp] = bv; argI[warp] = bi; }
    __syncthreads();
    if (warp == 0) {
        bv = argV[lane]; bi = argI[lane];
        #pragma unroll
        for (int o = 16; o; o >>= 1) {
            float ov = __shfl_down_sync(0xffffffffu, bv, o);
            int   oi = __shfl_down_sync(0xffffffffu, bi, o);
            if (ov > bv || (ov == bv && oi < bi)) { bv = ov; bi = oi; }
        }
        if (lane == 0) out_ids[row] = (float)bi;
    }
}

extern "C" void kernel_launch(void* const* d_in, const int* in_sizes, int n_in,
                              void* d_out, int out_size) {
    const float* logits = (const float*)d_in[0];
    const int*   k      = (const int*)  d_in[1];
    const float* p      = (const float*)d_in[2];
    const float* q      = (const float*)d_in[3];
    float* out = (float*)d_out;
    float* out_ids   = out;
    float* out_probs = out + BB;
    topk_topp_sample_kernel<<<BB, TPB>>>(logits, k, p, q, out_ids, out_probs);
}

// round 8
// speedup vs baseline: 1.5971x; 1.5971x over previous
#include <cuda_runtime.h>
#include <math.h>

#define BB   128
#define VV   128000
#define NV4  (VV/4)
#define TPB  1024
#define CAND_MAX 3968

// monotonic float -> ordered uint32
__device__ __forceinline__ unsigned f2ord(float f) {
    unsigned u = __float_as_uint(f);
    return (u & 0x80000000u) ? ~u : (u | 0x80000000u);
}
// inverse (floor decode); NaN-zone keys self-correct the bisection
__device__ __forceinline__ float ord2f_floor(unsigned o) {
    if (o <= 0x007FFFFFu) return -__int_as_float(0x7f800000); // -inf: take all
    return (o & 0x80000000u) ? __uint_as_float(o ^ 0x80000000u)
                             : __uint_as_float(~o);
}

__device__ float blk_excl_scan(float v, float* tmp) {
    __syncthreads();
    int lane = threadIdx.x & 31, w = threadIdx.x >> 5;
    float x = v;
    #pragma unroll
    for (int o = 1; o < 32; o <<= 1) {
        float y = __shfl_up_sync(0xffffffffu, x, o);
        if (lane >= o) x += y;
    }
    if (lane == 31) tmp[w] = x;
    __syncthreads();
    if (w == 0) {
        float s = tmp[lane];
        #pragma unroll
        for (int o = 1; o < 32; o <<= 1) {
            float y = __shfl_up_sync(0xffffffffu, s, o);
            if (lane >= o) s += y;
        }
        tmp[lane] = s;
    }
    __syncthreads();
    float pre = (w > 0) ? tmp[w - 1] : 0.0f;
    return pre + x - v;
}

__device__ float blk_reduce_sum(float v, float* tmp) {
    __syncthreads();
    int lane = threadIdx.x & 31, w = threadIdx.x >> 5;
    #pragma unroll
    for (int o = 16; o; o >>= 1) v += __shfl_xor_sync(0xffffffffu, v, o);
    if (lane == 0) tmp[w] = v;
    __syncthreads();
    if (w == 0) {
        float x = tmp[lane];
        #pragma unroll
        for (int o = 16; o; o >>= 1) x += __shfl_xor_sync(0xffffffffu, x, o);
        if (lane == 0) tmp[0] = x;
    }
    __syncthreads();
    return tmp[0];
}

__device__ float blk_reduce_max(float v, float* tmp) {
    __syncthreads();
    int lane = threadIdx.x & 31, w = threadIdx.x >> 5;
    #pragma unroll
    for (int o = 16; o; o >>= 1) v = fmaxf(v, __shfl_xor_sync(0xffffffffu, v, o));
    if (lane == 0) tmp[w] = v;
    __syncthreads();
    if (w == 0) {
        float x = tmp[lane];
        #pragma unroll
        for (int o = 16; o; o >>= 1) x = fmaxf(x, __shfl_xor_sync(0xffffffffu, x, o));
        if (lane == 0) tmp[0] = x;
    }
    __syncthreads();
    return tmp[0];
}

struct CrossRes { int bin; float above; bool found; };

template<int NBINS>
__device__ CrossRes find_crossing(const float* wgt, float target, float* scanTmp,
                                  int* sh_r, int* sh_b, float* sh_c) {
    __syncthreads();
    const int bpt = (NBINS + TPB - 1) / TPB;
    int t = threadIdx.x;
    float s = 0.f;
    #pragma unroll
    for (int j = 0; j < bpt; j++) {
        int r = t * bpt + j;
        if (r < NBINS) s += wgt[NBINS - 1 - r];
    }
    float P = blk_excl_scan(s, scanTmp);
    if (t == 0) *sh_r = 0x7fffffff;
    __syncthreads();
    float cum = P;
    #pragma unroll
    for (int j = 0; j < bpt; j++) {
        int r = t * bpt + j;
        if (r < NBINS) {
            float wv = wgt[NBINS - 1 - r];
            if (cum < target && cum + wv >= target) atomicMin(sh_r, r);
            cum += wv;
        }
    }
    __syncthreads();
    int fr = *sh_r;
    if (fr != 0x7fffffff) {
        cum = P;
        #pragma unroll
        for (int j = 0; j < bpt; j++) {
            int r = t * bpt + j;
            if (r < NBINS) {
                float wv = wgt[NBINS - 1 - r];
                if (r == fr) { *sh_b = NBINS - 1 - r; *sh_c = cum; }
                cum += wv;
            }
        }
    }
    __syncthreads();
    CrossRes res;
    res.found = (fr != 0x7fffffff);
    res.bin = res.found ? *sh_b : 0;
    res.above = res.found ? *sh_c : 0.f;
    return res;
}

__global__ void __launch_bounds__(TPB, 1)
topk_topp_sample_kernel(const float* __restrict__ logits,
                        const int*   __restrict__ karr,
                        const float* __restrict__ parr,
                        const float* __restrict__ qarr,
                        float* __restrict__ out_ids,
                        float* __restrict__ out_probs)
{
    __shared__ float cand[CAND_MAX];      // 15.5 KB
    __shared__ int   candIdx[CAND_MAX];   // 15.5 KB
    __shared__ float histbuf[4096];       // 16 KB, aliased across all levels
    __shared__ float scanTmp[32];
    __shared__ float redTmp[32];
    __shared__ int   shr; __shared__ int shb; __shared__ float shc;
    __shared__ int   shn;
    __shared__ float argV[32]; __shared__ int argI[32];

    const int row = blockIdx.x;
    const int t = threadIdx.x;
    const int lane = t & 31, warp = t >> 5;
    const float* lg = logits + (long long)row * VV;
    const float* qr = qarr   + (long long)row * VV;
    float* pro = out_probs + (long long)row * VV;
    const int   k = karr[row];
    const float p = parr[row];

    const float4* lg4 = reinterpret_cast<const float4*>(lg);

    // ---- Phase A: speculative-floor compaction (one atomic per warp per float4) ----
    // NV4=32000: last partial iteration covers threads 0..255 = warps 0-7 whole,
    // so full-mask ballots are warp-uniform.
    unsigned loK = 0u, hiK = 0xFFFFFFFFu, fK = 0xC0000000u;  // f2ord(2.0f)
    int n = 0;
    for (int iter = 0; iter < 20; iter++) {
        if (t == 0) shn = 0;
        __syncthreads();
        const float ffloor = ord2f_floor(fK);
        for (int i = t; i < NV4; i += TPB) {
            float4 v = lg4[i];
            float xs[4] = {v.x, v.y, v.z, v.w};
            unsigned mm[4];
            #pragma unroll
            for (int j = 0; j < 4; j++)
                mm[j] = __ballot_sync(0xffffffffu, xs[j] >= ffloor);
            int tot = __popc(mm[0]) + __popc(mm[1]) + __popc(mm[2]) + __popc(mm[3]);
            if (tot) {
                int base = 0;
                if (lane == 0) base = atomicAdd(&shn, tot);
                base = __shfl_sync(0xffffffffu, base, 0);
                int off = base;
                #pragma unroll
                for (int j = 0; j < 4; j++) {
                    if ((mm[j] >> lane) & 1u) {
                        int o2 = off + __popc(mm[j] & ((1u << lane) - 1u));
                        if (o2 < CAND_MAX) { cand[o2] = xs[j]; candIdx[o2] = i * 4 + j; }
                    }
                    off += __popc(mm[j]);
                }
            }
        }
        __syncthreads();
        n = shn;
        if (n >= k && n <= CAND_MAX) break;
        if (n > CAND_MAX) { loK = fK; fK = fK + ((hiK - fK) >> 1); }
        else              { hiK = fK; fK = loK + ((fK - loK) >> 1); }
        __syncthreads();
    }
    if (n > CAND_MAX) n = CAND_MAX;

    // ---- Early zero-fill of probs (fire-and-forget; drains during selection) ----
    float4* pr4 = reinterpret_cast<float4*>(pro);
    const float4 z4 = make_float4(0.f, 0.f, 0.f, 0.f);
    for (int i = t; i < NV4; i += TPB) pr4[i] = z4;

    // ---- Row max from candidates (global max is in cand) ----
    float mx = -3.4e38f;
    for (int i = t; i < n; i += TPB) mx = fmaxf(mx, cand[i]);
    float M = blk_reduce_max(mx, redTmp);

    // ---- Exact top-k threshold: 12/12/8 count radix (spread bins) ----
    float target = (float)k;
    // level 1: bits [31:20]
    __syncthreads();
    for (int i = t; i < 4096; i += TPB) histbuf[i] = 0.f;
    __syncthreads();
    for (int i = t; i < n; i += TPB)
        atomicAdd(&histbuf[f2ord(cand[i]) >> 20], 1.f);
    CrossRes c1r = find_crossing<4096>(histbuf, target, scanTmp, &shr, &shb, &shc);
    target -= c1r.above;
    unsigned pfx12 = (unsigned)c1r.bin;
    // level 2: bits [19:8] within pfx12
    __syncthreads();
    for (int i = t; i < 4096; i += TPB) histbuf[i] = 0.f;
    __syncthreads();
    for (int i = t; i < n; i += TPB) {
        unsigned ou = f2ord(cand[i]);
        if ((ou >> 20) == pfx12) atomicAdd(&histbuf[(ou >> 8) & 4095u], 1.f);
    }
    CrossRes c2r = find_crossing<4096>(histbuf, target, scanTmp, &shr, &shb, &shc);
    target -= c2r.above;
    unsigned pfx24 = (pfx12 << 12) | (unsigned)c2r.bin;
    // level 3: bits [7:0] within pfx24 (use first 256 bins of histbuf)
    __syncthreads();
    if (t < 256) histbuf[t] = 0.f;
    __syncthreads();
    for (int i = t; i < n; i += TPB) {
        unsigned ou = f2ord(cand[i]);
        if ((ou >> 8) == pfx24) atomicAdd(&histbuf[ou & 255u], 1.f);
    }
    CrossRes c3r = find_crossing<256>(histbuf, target, scanTmp, &shr, &shb, &shc);
    const unsigned thr_ou = (pfx24 << 8) | (unsigned)c3r.bin;

    // ---- Z_k over top-k set ----
    float zs = 0.f;
    for (int i = t; i < n; i += TPB) {
        float x = cand[i];
        if (f2ord(x) >= thr_ou) zs += __expf(x - M);
    }
    float Zk = blk_reduce_sum(zs, redTmp);
    float T = p * Zk;

    // ---- Weighted 12/10/10 radix descent for top-p cutoff ----
    unsigned t_ou;
    {
        __syncthreads();
        for (int i = t; i < 4096; i += TPB) histbuf[i] = 0.f;
        __syncthreads();
        for (int i = t; i < n; i += TPB) {
            float x = cand[i]; unsigned ou = f2ord(x);
            if (ou >= thr_ou) atomicAdd(&histbuf[ou >> 20], __expf(x - M));
        }
        CrossRes w1 = find_crossing<4096>(histbuf, T, scanTmp, &shr, &shb, &shc);
        if (!w1.found) {
            t_ou = thr_ou;
        } else {
            float Tb = T - w1.above;
            unsigned wc1 = (unsigned)w1.bin;
            __syncthreads();
            if (t < 1024) histbuf[t] = 0.f;
            __syncthreads();
            for (int i = t; i < n; i += TPB) {
                float x = cand[i]; unsigned ou = f2ord(x);
                if (ou >= thr_ou && (ou >> 20) == wc1)
                    atomicAdd(&histbuf[(ou >> 10) & 1023u], __expf(x - M));
            }
            CrossRes w2 = find_crossing<1024>(histbuf, Tb, scanTmp, &shr, &shb, &shc);
            if (!w2.found) {
                t_ou = wc1 << 20;
            } else {
                float T2 = Tb - w2.above;
                unsigned pw = (wc1 << 10) | (unsigned)w2.bin;
                __syncthreads();
                if (t < 1024) histbuf[t] = 0.f;
                __syncthreads();
                for (int i = t; i < n; i += TPB) {
                    float x = cand[i]; unsigned ou = f2ord(x);
                    if (ou >= thr_ou && (ou >> 10) == pw)
                        atomicAdd(&histbuf[ou & 1023u], __expf(x - M));
                }
                CrossRes w3 = find_crossing<1024>(histbuf, T2, scanTmp, &shr, &shb, &shc);
                t_ou = w3.found ? ((pw << 10) | (unsigned)w3.bin) : (pw << 10);
            }
        }
    }
    const unsigned f_ou = (t_ou > thr_ou) ? t_ou : thr_ou;
    const float ford = ord2f_floor(f_ou);

    // ---- Final normalizer ----
    float zf = 0.f;
    for (int i = t; i < n; i += TPB) {
        float x = cand[i];
        if (x >= ford) zf += __expf(x - M);
    }
    float Z = blk_reduce_sum(zf, redTmp);
    float invZ = 1.0f / Z;
    // (all threads passed >=1 __syncthreads since zero-fill -> zeros are ordered
    //  before the scatter below within this block)

    // ---- Sparse scatter of kept probs + fused Gumbel-max argmax ----
    float bv = -1.f; int bi = 0x7fffffff;
    for (int i = t; i < n; i += TPB) {
        float x = cand[i];
        if (x >= ford) {
            int idx = candIdx[i];
            float prob = __expf(x - M) * invZ;
            pro[idx] = prob;
            float ratio = prob / (-__logf(qr[idx]));
            if (ratio > bv || (ratio == bv && idx < bi)) { bv = ratio; bi = idx; }
        }
    }
    #pragma unroll
    for (int o = 16; o; o >>= 1) {
        float ov = __shfl_down_sync(0xffffffffu, bv, o);
        int   oi = __shfl_down_sync(0xffffffffu, bi, o);
        if (ov > bv || (ov == bv && oi < bi)) { bv = ov; bi = oi; }
    }
    if (lane == 0) { argV[warp] = bv; argI[warp] = bi; }
    __syncthreads();
    if (warp == 0) {
        bv = argV[lane]; bi = argI[lane];
        #pragma unroll
        for (int o = 16; o; o >>= 1) {
            float ov = __shfl_down_sync(0xffffffffu, bv, o);
            int   oi = __shfl_down_sync(0xffffffffu, bi, o);
            if (ov > bv || (ov == bv && oi < bi)) { bv = ov; bi = oi; }
        }
        if (lane == 0) out_ids[row] = (float)bi;
    }
}

extern "C" void kernel_launch(void* const* d_in, const int* in_sizes, int n_in,
                              void* d_out, int out_size) {
    const float* logits = (const float*)d_in[0];
    const int*   k      = (const int*)  d_in[1];
    const float* p      = (const float*)d_in[2];
    const float* q      = (const float*)d_in[3];
    float* out = (float*)d_out;
    float* out_ids   = out;
    float* out_probs = out + BB;
    topk_topp_sample_kernel<<<BB, TPB>>>(logits, k, p, q, out_ids, out_probs);
}

// round 9
// speedup vs baseline: 1.7029x; 1.0662x over previous
#include <cuda_runtime.h>
#include <math.h>

#define BB   128
#define VV   128000
#define NV4  (VV/4)
#define TPB  1024
#define CAND_MAX 3968

// monotonic float -> ordered uint32
__device__ __forceinline__ unsigned f2ord(float f) {
    unsigned u = __float_as_uint(f);
    return (u & 0x80000000u) ? ~u : (u | 0x80000000u);
}
// inverse (floor decode); NaN-zone keys self-correct the bisection
__device__ __forceinline__ float ord2f_floor(unsigned o) {
    if (o <= 0x007FFFFFu) return -__int_as_float(0x7f800000); // -inf: take all
    return (o & 0x80000000u) ? __uint_as_float(o ^ 0x80000000u)
                             : __uint_as_float(~o);
}

__device__ float blk_excl_scan(float v, float* tmp) {
    __syncthreads();
    int lane = threadIdx.x & 31, w = threadIdx.x >> 5;
    float x = v;
    #pragma unroll
    for (int o = 1; o < 32; o <<= 1) {
        float y = __shfl_up_sync(0xffffffffu, x, o);
        if (lane >= o) x += y;
    }
    if (lane == 31) tmp[w] = x;
    __syncthreads();
    if (w == 0) {
        float s = tmp[lane];
        #pragma unroll
        for (int o = 1; o < 32; o <<= 1) {
            float y = __shfl_up_sync(0xffffffffu, s, o);
            if (lane >= o) s += y;
        }
        tmp[lane] = s;
    }
    __syncthreads();
    float pre = (w > 0) ? tmp[w - 1] : 0.0f;
    return pre + x - v;
}

__device__ float blk_reduce_sum(float v, float* tmp) {
    __syncthreads();
    int lane = threadIdx.x & 31, w = threadIdx.x >> 5;
    #pragma unroll
    for (int o = 16; o; o >>= 1) v += __shfl_xor_sync(0xffffffffu, v, o);
    if (lane == 0) tmp[w] = v;
    __syncthreads();
    if (w == 0) {
        float x = tmp[lane];
        #pragma unroll
        for (int o = 16; o; o >>= 1) x += __shfl_xor_sync(0xffffffffu, x, o);
        if (lane == 0) tmp[0] = x;
    }
    __syncthreads();
    return tmp[0];
}

__device__ float blk_reduce_max(float v, float* tmp) {
    __syncthreads();
    int lane = threadIdx.x & 31, w = threadIdx.x >> 5;
    #pragma unroll
    for (int o = 16; o; o >>= 1) v = fmaxf(v, __shfl_xor_sync(0xffffffffu, v, o));
    if (lane == 0) tmp[w] = v;
    __syncthreads();
    if (w == 0) {
        float x = tmp[lane];
        #pragma unroll
        for (int o = 16; o; o >>= 1) x = fmaxf(x, __shfl_xor_sync(0xffffffffu, x, o));
        if (lane == 0) tmp[0] = x;
    }
    __syncthreads();
    return tmp[0];
}

struct CrossRes { int bin; float above; bool found; };

template<int NBINS>
__device__ CrossRes find_crossing(const float* wgt, float target, float* scanTmp,
                                  int* sh_r, int* sh_b, float* sh_c) {
    __syncthreads();
    const int bpt = (NBINS + TPB - 1) / TPB;
    int t = threadIdx.x;
    float s = 0.f;
    #pragma unroll
    for (int j = 0; j < bpt; j++) {
        int r = t * bpt + j;
        if (r < NBINS) s += wgt[NBINS - 1 - r];
    }
    float P = blk_excl_scan(s, scanTmp);
    if (t == 0) *sh_r = 0x7fffffff;
    __syncthreads();
    float cum = P;
    #pragma unroll
    for (int j = 0; j < bpt; j++) {
        int r = t * bpt + j;
        if (r < NBINS) {
            float wv = wgt[NBINS - 1 - r];
            if (cum < target && cum + wv >= target) atomicMin(sh_r, r);
            cum += wv;
        }
    }
    __syncthreads();
    int fr = *sh_r;
    if (fr != 0x7fffffff) {
        cum = P;
        #pragma unroll
        for (int j = 0; j < bpt; j++) {
            int r = t * bpt + j;
            if (r < NBINS) {
                float wv = wgt[NBINS - 1 - r];
                if (r == fr) { *sh_b = NBINS - 1 - r; *sh_c = cum; }
                cum += wv;
            }
        }
    }
    __syncthreads();
    CrossRes res;
    res.found = (fr != 0x7fffffff);
    res.bin = res.found ? *sh_b : 0;
    res.above = res.found ? *sh_c : 0.f;
    return res;
}

// total of a hist, bins-only (no candidate pass)
template<int NBINS>
__device__ float hist_total(const float* wgt, float* redTmp) {
    __syncthreads();
    const int bpt = (NBINS + TPB - 1) / TPB;
    int t = threadIdx.x;
    float s = 0.f;
    #pragma unroll
    for (int j = 0; j < bpt; j++) {
        int r = t * bpt + j;
        if (r < NBINS) s += wgt[r];
    }
    return blk_reduce_sum(s, redTmp);
}

__global__ void __launch_bounds__(TPB, 1)
topk_topp_sample_kernel(const float* __restrict__ logits,
                        const int*   __restrict__ karr,
                        const float* __restrict__ parr,
                        const float* __restrict__ qarr,
                        float* __restrict__ out_ids,
                        float* __restrict__ out_probs)
{
    __shared__ float cand[CAND_MAX];      // 15.5 KB
    __shared__ int   candIdx[CAND_MAX];   // 15.5 KB
    __shared__ float histbuf[4096];       // 16 KB, aliased across all levels
    __shared__ float scanTmp[32];
    __shared__ float redTmp[32];
    __shared__ int   shr; __shared__ int shb; __shared__ float shc;
    __shared__ int   shn;
    __shared__ float argV[32]; __shared__ int argI[32];

    const int row = blockIdx.x;
    const int t = threadIdx.x;
    const int lane = t & 31, warp = t >> 5;
    const float* lg = logits + (long long)row * VV;
    const float* qr = qarr   + (long long)row * VV;
    float* pro = out_probs + (long long)row * VV;
    const int   k = karr[row];
    const float p = parr[row];

    const float4* lg4 = reinterpret_cast<const float4*>(lg);
    float4* pr4 = reinterpret_cast<float4*>(pro);

    // ---- Zero-fill probs first: pure stores overlap later reads ----
    {
        const float4 z4 = make_float4(0.f, 0.f, 0.f, 0.f);
        int i = t;
        #pragma unroll 4
        for (; i < NV4; i += TPB) pr4[i] = z4;
    }

    // ---- Phase A: ILP-2 chunked compaction, warp-scan offsets ----
    const float NEG = -__int_as_float(0x7f800000);   // -inf sentinel (never taken)
    unsigned loK = 0u, hiK = 0xFFFFFFFFu, fK = 0xC0000000u;  // f2ord(2.0f)
    int n = 0;
    for (int iter = 0; iter < 20; iter++) {
        if (t == 0) shn = 0;
        __syncthreads();
        const float ffloor = ord2f_floor(fK);
        for (int base = 0; base < NV4; base += 2 * TPB) {
            int i0 = base + t, i1 = i0 + TPB;
            float4 v0 = (i0 < NV4) ? lg4[i0] : make_float4(NEG, NEG, NEG, NEG);
            float4 v1 = (i1 < NV4) ? lg4[i1] : make_float4(NEG, NEG, NEG, NEG);
            bool p00 = v0.x >= ffloor, p01 = v0.y >= ffloor,
                 p02 = v0.z >= ffloor, p03 = v0.w >= ffloor;
            bool p10 = v1.x >= ffloor, p11 = v1.y >= ffloor,
                 p12 = v1.z >= ffloor, p13 = v1.w >= ffloor;
            int cnt = (int)p00 + p01 + p02 + p03 + p10 + p11 + p12 + p13;
            // warp inclusive scan of cnt
            int inc = cnt;
            #pragma unroll
            for (int o = 1; o < 32; o <<= 1) {
                int y = __shfl_up_sync(0xffffffffu, inc, o);
                if (lane >= o) inc += y;
            }
            int wtot = __shfl_sync(0xffffffffu, inc, 31);
            int wbase = 0;
            if (wtot) {
                if (lane == 31) wbase = atomicAdd(&shn, wtot);
                wbase = __shfl_sync(0xffffffffu, wbase, 31);
                int off = wbase + inc - cnt;
                int id0 = i0 * 4, id1 = i1 * 4;
                if (p00 && off < CAND_MAX) { cand[off] = v0.x; candIdx[off] = id0;     off++; }
                if (p01 && off < CAND_MAX) { cand[off] = v0.y; candIdx[off] = id0 + 1; off++; }
                if (p02 && off < CAND_MAX) { cand[off] = v0.z; candIdx[off] = id0 + 2; off++; }
                if (p03 && off < CAND_MAX) { cand[off] = v0.w; candIdx[off] = id0 + 3; off++; }
                if (p10 && off < CAND_MAX) { cand[off] = v1.x; candIdx[off] = id1;     off++; }
                if (p11 && off < CAND_MAX) { cand[off] = v1.y; candIdx[off] = id1 + 1; off++; }
                if (p12 && off < CAND_MAX) { cand[off] = v1.z; candIdx[off] = id1 + 2; off++; }
                if (p13 && off < CAND_MAX) { cand[off] = v1.w; candIdx[off] = id1 + 3; off++; }
            }
        }
        __syncthreads();
        n = shn;
        if (n >= k && n <= CAND_MAX) break;
        if (n > CAND_MAX) { loK = fK; fK = fK + ((hiK - fK) >> 1); }
        else              { hiK = fK; fK = loK + ((fK - loK) >> 1); }
        __syncthreads();
    }
    if (n > CAND_MAX) n = CAND_MAX;

    // ---- Row max from candidates ----
    float mx = -3.4e38f;
    for (int i = t; i < n; i += TPB) mx = fmaxf(mx, cand[i]);
    float M = blk_reduce_max(mx, redTmp);

    // ---- Exact top-k threshold: 12/12/8 count radix ----
    float target = (float)k;
    __syncthreads();
    for (int i = t; i < 4096; i += TPB) histbuf[i] = 0.f;
    __syncthreads();
    for (int i = t; i < n; i += TPB)
        atomicAdd(&histbuf[f2ord(cand[i]) >> 20], 1.f);
    CrossRes c1r = find_crossing<4096>(histbuf, target, scanTmp, &shr, &shb, &shc);
    target -= c1r.above;
    unsigned pfx12 = (unsigned)c1r.bin;
    __syncthreads();
    for (int i = t; i < 4096; i += TPB) histbuf[i] = 0.f;
    __syncthreads();
    for (int i = t; i < n; i += TPB) {
        unsigned ou = f2ord(cand[i]);
        if ((ou >> 20) == pfx12) atomicAdd(&histbuf[(ou >> 8) & 4095u], 1.f);
    }
    CrossRes c2r = find_crossing<4096>(histbuf, target, scanTmp, &shr, &shb, &shc);
    target -= c2r.above;
    unsigned pfx24 = (pfx12 << 12) | (unsigned)c2r.bin;
    __syncthreads();
    if (t < 256) histbuf[t] = 0.f;
    __syncthreads();
    for (int i = t; i < n; i += TPB) {
        unsigned ou = f2ord(cand[i]);
        if ((ou >> 8) == pfx24) atomicAdd(&histbuf[ou & 255u], 1.f);
    }
    CrossRes c3r = find_crossing<256>(histbuf, target, scanTmp, &shr, &shb, &shc);
    const unsigned thr_ou = (pfx24 << 8) | (unsigned)c3r.bin;

    // ---- Weighted 12/10/10 descent; Zk and Zf fused into hist totals ----
    float Zk, zf;
    unsigned t_ou;
    {
        __syncthreads();
        for (int i = t; i < 4096; i += TPB) histbuf[i] = 0.f;
        __syncthreads();
        for (int i = t; i < n; i += TPB) {
            float x = cand[i]; unsigned ou = f2ord(x);
            if (ou >= thr_ou) atomicAdd(&histbuf[ou >> 20], __expf(x - M));
        }
        Zk = hist_total<4096>(histbuf, redTmp);           // Zk fused: total of hist
        float T = p * Zk;
        CrossRes w1 = find_crossing<4096>(histbuf, T, scanTmp, &shr, &shb, &shc);
        if (!w1.found) {
            t_ou = thr_ou; zf = Zk;
        } else {
            float ab1 = w1.above;
            unsigned wc1 = (unsigned)w1.bin;
            __syncthreads();
            if (t < 1024) histbuf[t] = 0.f;
            __syncthreads();
            for (int i = t; i < n; i += TPB) {
                float x = cand[i]; unsigned ou = f2ord(x);
                if (ou >= thr_ou && (ou >> 20) == wc1)
                    atomicAdd(&histbuf[(ou >> 10) & 1023u], __expf(x - M));
            }
            float tot2 = hist_total<1024>(histbuf, redTmp);
            CrossRes w2 = find_crossing<1024>(histbuf, T - ab1, scanTmp, &shr, &shb, &shc);
            if (!w2.found) {
                t_ou = wc1 << 20; zf = ab1 + tot2;
            } else {
                float ab2 = w2.above;
                unsigned pw = (wc1 << 10) | (unsigned)w2.bin;
                __syncthreads();
                if (t < 1024) histbuf[t] = 0.f;
                __syncthreads();
                for (int i = t; i < n; i += TPB) {
                    float x = cand[i]; unsigned ou = f2ord(x);
                    if (ou >= thr_ou && (ou >> 10) == pw)
                        atomicAdd(&histbuf[ou & 1023u], __expf(x - M));
                }
                float tot3 = hist_total<1024>(histbuf, redTmp);
                CrossRes w3 = find_crossing<1024>(histbuf, T - ab1 - ab2,
                                                  scanTmp, &shr, &shb, &shc);
                if (!w3.found) {
                    t_ou = pw << 10; zf = ab1 + ab2 + tot3;
                } else {
                    t_ou = (pw << 10) | (unsigned)w3.bin;
                    zf = ab1 + ab2 + w3.above + histbuf[w3.bin];
                }
            }
        }
    }
    if (t_ou <= thr_ou) zf = Zk;                 // f_ou = thr_ou -> kept = top-k set
    const unsigned f_ou = (t_ou > thr_ou) ? t_ou : thr_ou;
    const float ford = ord2f_floor(f_ou);
    const float invZ = 1.0f / zf;

    // ---- Sparse scatter of kept probs + fused Gumbel-max argmax ----
    // (many __syncthreads since zero-fill -> block-level store ordering holds)
    float bv = -1.f; int bi = 0x7fffffff;
    for (int i = t; i < n; i += TPB) {
        float x = cand[i];
        if (x >= ford) {
            int idx = candIdx[i];
            float prob = __expf(x - M) * invZ;
            pro[idx] = prob;
            float ratio = prob / (-__logf(qr[idx]));
            if (ratio > bv || (ratio == bv && idx < bi)) { bv = ratio; bi = idx; }
        }
    }
    #pragma unroll
    for (int o = 16; o; o >>= 1) {
        float ov = __shfl_down_sync(0xffffffffu, bv, o);
        int   oi = __shfl_down_sync(0xffffffffu, bi, o);
        if (ov > bv || (ov == bv && oi < bi)) { bv = ov; bi = oi; }
    }
    if (lane == 0) { argV[warp] = bv; argI[warp] = bi; }
    __syncthreads();
    if (warp == 0) {
        bv = argV[lane]; bi = argI[lane];
        #pragma unroll
        for (int o = 16; o; o >>= 1) {
            float ov = __shfl_down_sync(0xffffffffu, bv, o);
            int   oi = __shfl_down_sync(0xffffffffu, bi, o);
            if (ov > bv || (ov == bv && oi < bi)) { bv = ov; bi = oi; }
        }
        if (lane == 0) out_ids[row] = (float)bi;
    }
}

extern "C" void kernel_launch(void* const* d_in, const int* in_sizes, int n_in,
                              void* d_out, int out_size) {
    const float* logits = (const float*)d_in[0];
    const int*   k      = (const int*)  d_in[1];
    const float* p      = (const float*)d_in[2];
    const float* q      = (const float*)d_in[3];
    float* out = (float*)d_out;
    float* out_ids   = out;
    float* out_probs = out + BB;
    topk_topp_sample_kernel<<<BB, TPB>>>(logits, k, p, q, out_ids, out_probs);
}

// round 10
// speedup vs baseline: 1.7809x; 1.0458x over previous
#include <cuda_runtime.h>
#include <math.h>

#define BB   128
#define VV   128000
#define NV4  (VV/4)
#define TPB  1024
#define CAND_MAX 3968

// monotonic float -> ordered uint32
__device__ __forceinline__ unsigned f2ord(float f) {
    unsigned u = __float_as_uint(f);
    return (u & 0x80000000u) ? ~u : (u | 0x80000000u);
}
// inverse (floor decode); NaN-zone keys self-correct the bisection
__device__ __forceinline__ float ord2f_floor(unsigned o) {
    if (o <= 0x007FFFFFu) return -__int_as_float(0x7f800000); // -inf: take all
    return (o & 0x80000000u) ? __uint_as_float(o ^ 0x80000000u)
                             : __uint_as_float(~o);
}

__device__ float blk_excl_scan(float v, float* tmp) {
    __syncthreads();
    int lane = threadIdx.x & 31, w = threadIdx.x >> 5;
    float x = v;
    #pragma unroll
    for (int o = 1; o < 32; o <<= 1) {
        float y = __shfl_up_sync(0xffffffffu, x, o);
        if (lane >= o) x += y;
    }
    if (lane == 31) tmp[w] = x;
    __syncthreads();
    if (w == 0) {
        float s = tmp[lane];
        #pragma unroll
        for (int o = 1; o < 32; o <<= 1) {
            float y = __shfl_up_sync(0xffffffffu, s, o);
            if (lane >= o) s += y;
        }
        tmp[lane] = s;
    }
    __syncthreads();
    float pre = (w > 0) ? tmp[w - 1] : 0.0f;
    return pre + x - v;
}

__device__ float blk_reduce_sum(float v, float* tmp) {
    __syncthreads();
    int lane = threadIdx.x & 31, w = threadIdx.x >> 5;
    #pragma unroll
    for (int o = 16; o; o >>= 1) v += __shfl_xor_sync(0xffffffffu, v, o);
    if (lane == 0) tmp[w] = v;
    __syncthreads();
    if (w == 0) {
        float x = tmp[lane];
        #pragma unroll
        for (int o = 16; o; o >>= 1) x += __shfl_xor_sync(0xffffffffu, x, o);
        if (lane == 0) tmp[0] = x;
    }
    __syncthreads();
    return tmp[0];
}

__device__ float blk_reduce_max(float v, float* tmp) {
    __syncthreads();
    int lane = threadIdx.x & 31, w = threadIdx.x >> 5;
    #pragma unroll
    for (int o = 16; o; o >>= 1) v = fmaxf(v, __shfl_xor_sync(0xffffffffu, v, o));
    if (lane == 0) tmp[w] = v;
    __syncthreads();
    if (w == 0) {
        float x = tmp[lane];
        #pragma unroll
        for (int o = 16; o; o >>= 1) x = fmaxf(x, __shfl_xor_sync(0xffffffffu, x, o));
        if (lane == 0) tmp[0] = x;
    }
    __syncthreads();
    return tmp[0];
}

struct CrossRes { int bin; float above; bool found; };

template<int NBINS>
__device__ CrossRes find_crossing(const float* wgt, float target, float* scanTmp,
                                  int* sh_r, int* sh_b, float* sh_c) {
    __syncthreads();
    const int bpt = (NBINS + TPB - 1) / TPB;
    int t = threadIdx.x;
    float s = 0.f;
    #pragma unroll
    for (int j = 0; j < bpt; j++) {
        int r = t * bpt + j;
        if (r < NBINS) s += wgt[NBINS - 1 - r];
    }
    float P = blk_excl_scan(s, scanTmp);
    if (t == 0) *sh_r = 0x7fffffff;
    __syncthreads();
    float cum = P;
    #pragma unroll
    for (int j = 0; j < bpt; j++) {
        int r = t * bpt + j;
        if (r < NBINS) {
            float wv = wgt[NBINS - 1 - r];
            if (cum < target && cum + wv >= target) atomicMin(sh_r, r);
            cum += wv;
        }
    }
    __syncthreads();
    int fr = *sh_r;
    if (fr != 0x7fffffff) {
        cum = P;
        #pragma unroll
        for (int j = 0; j < bpt; j++) {
            int r = t * bpt + j;
            if (r < NBINS) {
                float wv = wgt[NBINS - 1 - r];
                if (r == fr) { *sh_b = NBINS - 1 - r; *sh_c = cum; }
                cum += wv;
            }
        }
    }
    __syncthreads();
    CrossRes res;
    res.found = (fr != 0x7fffffff);
    res.bin = res.found ? *sh_b : 0;
    res.above = res.found ? *sh_c : 0.f;
    return res;
}

// total of a hist, bins-only (no candidate pass)
template<int NBINS>
__device__ float hist_total(const float* wgt, float* redTmp) {
    __syncthreads();
    const int bpt = (NBINS + TPB - 1) / TPB;
    int t = threadIdx.x;
    float s = 0.f;
    #pragma unroll
    for (int j = 0; j < bpt; j++) {
        int r = t * bpt + j;
        if (r < NBINS) s += wgt[r];
    }
    return blk_reduce_sum(s, redTmp);
}

__global__ void __launch_bounds__(TPB, 1)
topk_topp_sample_kernel(const float* __restrict__ logits,
                        const int*   __restrict__ karr,
                        const float* __restrict__ parr,
                        const float* __restrict__ qarr,
                        float* __restrict__ out_ids,
                        float* __restrict__ out_probs)
{
    __shared__ float cand[CAND_MAX];      // 15.5 KB
    __shared__ int   candIdx[CAND_MAX];   // 15.5 KB
    __shared__ float histbuf[4096];       // 16 KB, aliased across all levels
    __shared__ float scanTmp[32];
    __shared__ float redTmp[32];
    __shared__ int   shr; __shared__ int shb; __shared__ float shc;
    __shared__ int   shn;
    __shared__ float argV[32]; __shared__ int argI[32];

    const int row = blockIdx.x;
    const int t = threadIdx.x;
    const int lane = t & 31, warp = t >> 5;
    const float* lg = logits + (long long)row * VV;
    const float* qr = qarr   + (long long)row * VV;
    float* pro = out_probs + (long long)row * VV;
    const int   k = karr[row];
    const float p = parr[row];

    const float4* lg4 = reinterpret_cast<const float4*>(lg);
    float4* pr4 = reinterpret_cast<float4*>(pro);

    // ---- Zero-fill probs first: pure stores overlap later reads ----
    {
        const float4 z4 = make_float4(0.f, 0.f, 0.f, 0.f);
        int i = t;
        #pragma unroll 4
        for (; i < NV4; i += TPB) pr4[i] = z4;
    }

    // ---- Phase A: ILP-4 compaction, warp-scan offsets, fused row max ----
    const float NEG = -__int_as_float(0x7f800000);   // -inf sentinel (never taken)
    unsigned loK = 0u, hiK = 0xFFFFFFFFu, fK = 0xC0000000u;  // f2ord(2.0f)
    int n = 0;
    float mx;
    for (int iter = 0; iter < 20; iter++) {
        if (t == 0) shn = 0;
        mx = -3.4e38f;
        __syncthreads();
        const float ffloor = ord2f_floor(fK);
        for (int base = 0; base < NV4; base += 4 * TPB) {
            int i0 = base + t, i1 = i0 + TPB, i2 = i1 + TPB, i3 = i2 + TPB;
            float4 v0 = (i0 < NV4) ? lg4[i0] : make_float4(NEG, NEG, NEG, NEG);
            float4 v1 = (i1 < NV4) ? lg4[i1] : make_float4(NEG, NEG, NEG, NEG);
            float4 v2 = (i2 < NV4) ? lg4[i2] : make_float4(NEG, NEG, NEG, NEG);
            float4 v3 = (i3 < NV4) ? lg4[i3] : make_float4(NEG, NEG, NEG, NEG);
            float xs[16] = { v0.x, v0.y, v0.z, v0.w,  v1.x, v1.y, v1.z, v1.w,
                             v2.x, v2.y, v2.z, v2.w,  v3.x, v3.y, v3.z, v3.w };
            unsigned pm = 0;   // 16-bit predicate mask
            int cnt = 0;
            #pragma unroll
            for (int j = 0; j < 16; j++) {
                bool tk = (xs[j] >= ffloor);
                pm |= (unsigned)tk << j;
                cnt += (int)tk;
                if (tk) mx = fmaxf(mx, xs[j]);
            }
            // warp inclusive scan of cnt
            int inc = cnt;
            #pragma unroll
            for (int o = 1; o < 32; o <<= 1) {
                int y = __shfl_up_sync(0xffffffffu, inc, o);
                if (lane >= o) inc += y;
            }
            int wtot = __shfl_sync(0xffffffffu, inc, 31);
            if (wtot) {
                int wbase = 0;
                if (lane == 31) wbase = atomicAdd(&shn, wtot);
                wbase = __shfl_sync(0xffffffffu, wbase, 31);
                int off = wbase + inc - cnt;
                #pragma unroll
                for (int j = 0; j < 16; j++) {
                    if ((pm >> j) & 1u) {
                        if (off < CAND_MAX) {
                            cand[off] = xs[j];
                            // element index: chunk (j/4) at stride TPB, lane j%4
                            candIdx[off] = (base + t + (j >> 2) * TPB) * 4 + (j & 3);
                        }
                        off++;
                    }
                }
            }
        }
        __syncthreads();
        n = shn;
        if (n >= k && n <= CAND_MAX) break;
        if (n > CAND_MAX) { loK = fK; fK = fK + ((hiK - fK) >> 1); }
        else              { hiK = fK; fK = loK + ((fK - loK) >> 1); }
        __syncthreads();
    }
    if (n > CAND_MAX) n = CAND_MAX;

    // ---- Row max (fused: reduce per-thread running max of taken elements) ----
    float M = blk_reduce_max(mx, redTmp);

    // ---- Exact top-k threshold: 12/12/8 count radix ----
    float target = (float)k;
    __syncthreads();
    for (int i = t; i < 4096; i += TPB) histbuf[i] = 0.f;
    __syncthreads();
    for (int i = t; i < n; i += TPB)
        atomicAdd(&histbuf[f2ord(cand[i]) >> 20], 1.f);
    CrossRes c1r = find_crossing<4096>(histbuf, target, scanTmp, &shr, &shb, &shc);
    target -= c1r.above;
    unsigned pfx12 = (unsigned)c1r.bin;
    __syncthreads();
    for (int i = t; i < 4096; i += TPB) histbuf[i] = 0.f;
    __syncthreads();
    for (int i = t; i < n; i += TPB) {
        unsigned ou = f2ord(cand[i]);
        if ((ou >> 20) == pfx12) atomicAdd(&histbuf[(ou >> 8) & 4095u], 1.f);
    }
    CrossRes c2r = find_crossing<4096>(histbuf, target, scanTmp, &shr, &shb, &shc);
    target -= c2r.above;
    unsigned pfx24 = (pfx12 << 12) | (unsigned)c2r.bin;
    __syncthreads();
    if (t < 256) histbuf[t] = 0.f;
    __syncthreads();
    for (int i = t; i < n; i += TPB) {
        unsigned ou = f2ord(cand[i]);
        if ((ou >> 8) == pfx24) atomicAdd(&histbuf[ou & 255u], 1.f);
    }
    CrossRes c3r = find_crossing<256>(histbuf, target, scanTmp, &shr, &shb, &shc);
    const unsigned thr_ou = (pfx24 << 8) | (unsigned)c3r.bin;

    // ---- Weighted 12/10/10 descent; Zk and Zf fused into hist totals ----
    float Zk, zf;
    unsigned t_ou;
    {
        __syncthreads();
        for (int i = t; i < 4096; i += TPB) histbuf[i] = 0.f;
        __syncthreads();
        for (int i = t; i < n; i += TPB) {
            float x = cand[i]; unsigned ou = f2ord(x);
            if (ou >= thr_ou) atomicAdd(&histbuf[ou >> 20], __expf(x - M));
        }
        Zk = hist_total<4096>(histbuf, redTmp);
        float T = p * Zk;
        CrossRes w1 = find_crossing<4096>(histbuf, T, scanTmp, &shr, &shb, &shc);
        if (!w1.found) {
            t_ou = thr_ou; zf = Zk;
        } else {
            float ab1 = w1.above;
            unsigned wc1 = (unsigned)w1.bin;
            __syncthreads();
            if (t < 1024) histbuf[t] = 0.f;
            __syncthreads();
            for (int i = t; i < n; i += TPB) {
                float x = cand[i]; unsigned ou = f2ord(x);
                if (ou >= thr_ou && (ou >> 20) == wc1)
                    atomicAdd(&histbuf[(ou >> 10) & 1023u], __expf(x - M));
            }
            float tot2 = hist_total<1024>(histbuf, redTmp);
            CrossRes w2 = find_crossing<1024>(histbuf, T - ab1, scanTmp, &shr, &shb, &shc);
            if (!w2.found) {
                t_ou = wc1 << 20; zf = ab1 + tot2;
            } else {
                float ab2 = w2.above;
                unsigned pw = (wc1 << 10) | (unsigned)w2.bin;
                __syncthreads();
                if (t < 1024) histbuf[t] = 0.f;
                __syncthreads();
                for (int i = t; i < n; i += TPB) {
                    float x = cand[i]; unsigned ou = f2ord(x);
                    if (ou >= thr_ou && (ou >> 10) == pw)
                        atomicAdd(&histbuf[ou & 1023u], __expf(x - M));
                }
                float tot3 = hist_total<1024>(histbuf, redTmp);
                CrossRes w3 = find_crossing<1024>(histbuf, T - ab1 - ab2,
                                                  scanTmp, &shr, &shb, &shc);
                if (!w3.found) {
                    t_ou = pw << 10; zf = ab1 + ab2 + tot3;
                } else {
                    t_ou = (pw << 10) | (unsigned)w3.bin;
                    zf = ab1 + ab2 + w3.above + histbuf[w3.bin];
                }
            }
        }
    }
    if (t_ou <= thr_ou) zf = Zk;                 // f_ou = thr_ou -> kept = top-k set
    const unsigned f_ou = (t_ou > thr_ou) ? t_ou : thr_ou;
    const float ford = ord2f_floor(f_ou);
    const float invZ = 1.0f / zf;

    // ---- Sparse scatter of kept probs + fused Gumbel-max argmax ----
    float bv = -1.f; int bi = 0x7fffffff;
    for (int i = t; i < n; i += TPB) {
        float x = cand[i];
        if (x >= ford) {
            int idx = candIdx[i];
            float prob = __expf(x - M) * invZ;
            pro[idx] = prob;
            float ratio = prob / (-__logf(qr[idx]));
            if (ratio > bv || (ratio == bv && idx < bi)) { bv = ratio; bi = idx; }
        }
    }
    #pragma unroll
    for (int o = 16; o; o >>= 1) {
        float ov = __shfl_down_sync(0xffffffffu, bv, o);
        int   oi = __shfl_down_sync(0xffffffffu, bi, o);
        if (ov > bv || (ov == bv && oi < bi)) { bv = ov; bi = oi; }
    }
    if (lane == 0) { argV[warp] = bv; argI[warp] = bi; }
    __syncthreads();
    if (warp == 0) {
        bv = argV[lane]; bi = argI[lane];
        #pragma unroll
        for (int o = 16; o; o >>= 1) {
            float ov = __shfl_down_sync(0xffffffffu, bv, o);
            int   oi = __shfl_down_sync(0xffffffffu, bi, o);
            if (ov > bv || (ov == bv && oi < bi)) { bv = ov; bi = oi; }
        }
        if (lane == 0) out_ids[row] = (float)bi;
    }
}

extern "C" void kernel_launch(void* const* d_in, const int* in_sizes, int n_in,
                              void* d_out, int out_size) {
    const float* logits = (const float*)d_in[0];
    const int*   k      = (const int*)  d_in[1];
    const float* p      = (const float*)d_in[2];
    const float* q      = (const float*)d_in[3];
    float* out = (float*)d_out;
    float* out_ids   = out;
    float* out_probs = out + BB;
    topk_topp_sample_kernel<<<BB, TPB>>>(logits, k, p, q, out_ids, out_probs);
}